// round 16
// baseline (speedup 1.0000x reference)
#include <cuda_runtime.h>

// Problem constants (from reference): WIDTH=1024, HALF=512, DEPTH=32, BATCH=32768.
// Row layout: 1024 floats = 256 float4; x0 = slots [0,128), x1 = slots [128,256).
// Math: each depth step applies [[1-w,w],[w,1-w]] = (1-w)I + wJ to pair (j, j+512).
// All steps for a given j commute; in the (s,d)=(x0+x1, x0-x1) eigenbasis the 32-step
// product has eigenvalue 1 on s and p_j = prod_i(1-2*w_ij) on d:
//   out0 = 0.5*s + (0.5*p_j)*d ;  out1 = 0.5*s - (0.5*p_j)*d
//
// R16 vs frozen R8 (36.3-37.2us @ ~74% DRAM): burst-granularity experiment.
// Each thread handles 2 CONSECUTIVE float4 slots -> 32B contiguous per thread,
// 256B contiguous per warp-access-pair -> longer same-direction DRAM runs /
// fewer row activates per byte. Only untested mechanism left; MLP (R9) and
// persistence (R12) were measured neutral/worse.

#define GROUPS_PER_ROW 8     // 128 float4 slots / 16 slots per group
#define SLOTPAIRS_GRP  8     // 8 slot-pairs = 16 float4 slots = 64 pairs per group
#define ROWS_PER_CHUNK 64
#define BLOCK_THREADS  512

__global__ void __launch_bounds__(BLOCK_THREADS, 4)
butterfly_fused_kernel(const float* __restrict__ X, const float* __restrict__ params,
                       float* __restrict__ out, int n_rows) {
    __shared__ float shp[64];   // 0.5 * p_j for this block's 64 pair indices

    const int tid   = threadIdx.x;                         // 0..511
    const int group = blockIdx.x & (GROUPS_PER_ROW - 1);   // slot group 0..7
    const int chunk = blockIdx.x >> 3;                     // row chunk 0..511

    // ---- Addressing: warp = 8 slot-pairs x 4 consecutive rows ----
    // Each thread covers 2 consecutive float4 slots = 32B contiguous per half-row;
    // warp access pair spans 2 contiguous 128B lines per row segment.
    const int sp_in = tid & (SLOTPAIRS_GRP - 1);           // slot-pair in group, 0..7
    const int r_in  = tid >> 3;                            // row within chunk, 0..63
    const int row   = chunk * ROWS_PER_CHUNK + r_in;
    const bool active = (row < n_rows);
    const int slot0 = group * 16 + sp_in * 2;              // first of 2 slots, 0..126

    const float4* x0p = reinterpret_cast<const float4*>(X   + (size_t)row * 1024) + slot0;
    const float4* x1p = reinterpret_cast<const float4*>(X   + (size_t)row * 1024 + 512) + slot0;
    float4*       o0p = reinterpret_cast<float4*>(out + (size_t)row * 1024) + slot0;
    float4*       o1p = reinterpret_cast<float4*>(out + (size_t)row * 1024 + 512) + slot0;

    // Issue all 4 streaming loads FIRST (adjacent-address pairs); prologue hides
    // under their latency.
    float4 x0a, x0b, x1a, x1b;
    if (active) {
        x0a = __ldcs(x0p);     x0b = __ldcs(x0p + 1);      // 32B contiguous
        x1a = __ldcs(x1p);     x1b = __ldcs(x1p + 1);
    }

    // ---- Prologue: cooperative p for pairs [group*64, group*64+64) ----
    // params slice = float4s [group*512, group*512+512); all 512 threads load one
    // float4 each (coalesced 8KB; 8 distinct slices chip-wide -> L2-resident).
    {
        float4 w = __ldg(reinterpret_cast<const float4*>(params) + group * 512 + tid);
        float q = fmaf(-2.0f, w.x, 1.0f) * fmaf(-2.0f, w.y, 1.0f)
                * fmaf(-2.0f, w.z, 1.0f) * fmaf(-2.0f, w.w, 1.0f);
        // Each params row (32 floats) = 8 consecutive threads; product-reduce within
        // the 8-thread segment (segments never cross a warp since 8 | 32).
        q *= __shfl_xor_sync(0xFFFFFFFF, q, 1);
        q *= __shfl_xor_sync(0xFFFFFFFF, q, 2);
        q *= __shfl_xor_sync(0xFFFFFFFF, q, 4);
        if ((tid & 7) == 0) shp[tid >> 3] = 0.5f * q;      // local pair index 0..63
    }
    __syncthreads();

    if (!active) return;

    // 8 half-p values for this thread's 2 slots: two LDS.128, conflict-free
    // (threads sharing sp_in broadcast).
    const float4 hpa = reinterpret_cast<const float4*>(shp)[sp_in * 2];
    const float4 hpb = reinterpret_cast<const float4*>(shp)[sp_in * 2 + 1];

    float4 o0a, o1a, o0b, o1b;
    {
        float hs, t;
        hs = 0.5f * (x0a.x + x1a.x); t = hpa.x * (x0a.x - x1a.x); o0a.x = hs + t; o1a.x = hs - t;
        hs = 0.5f * (x0a.y + x1a.y); t = hpa.y * (x0a.y - x1a.y); o0a.y = hs + t; o1a.y = hs - t;
        hs = 0.5f * (x0a.z + x1a.z); t = hpa.z * (x0a.z - x1a.z); o0a.z = hs + t; o1a.z = hs - t;
        hs = 0.5f * (x0a.w + x1a.w); t = hpa.w * (x0a.w - x1a.w); o0a.w = hs + t; o1a.w = hs - t;

        hs = 0.5f * (x0b.x + x1b.x); t = hpb.x * (x0b.x - x1b.x); o0b.x = hs + t; o1b.x = hs - t;
        hs = 0.5f * (x0b.y + x1b.y); t = hpb.y * (x0b.y - x1b.y); o0b.y = hs + t; o1b.y = hs - t;
        hs = 0.5f * (x0b.z + x1b.z); t = hpb.z * (x0b.z - x1b.z); o0b.z = hs + t; o1b.z = hs - t;
        hs = 0.5f * (x0b.w + x1b.w); t = hpb.w * (x0b.w - x1b.w); o0b.w = hs + t; o1b.w = hs - t;
    }

    // Adjacent-address store pairs: 32B contiguous per thread, 256B per warp run.
    __stcs(o0p, o0a);  __stcs(o0p + 1, o0b);
    __stcs(o1p, o1a);  __stcs(o1p + 1, o1b);
}

extern "C" void kernel_launch(void* const* d_in, const int* in_sizes, int n_in,
                              void* d_out, int out_size) {
    const float* X      = (const float*)d_in[0];   // [32768, 1024] fp32
    const float* params = (const float*)d_in[1];   // [512, 32] fp32
    float* out          = (float*)d_out;           // [32768, 1024] fp32

    const int n_rows = out_size / 1024;            // 32768
    const int chunks = (n_rows + ROWS_PER_CHUNK - 1) / ROWS_PER_CHUNK;
    butterfly_fused_kernel<<<GROUPS_PER_ROW * chunks, BLOCK_THREADS>>>(X, params, out, n_rows);
}